// round 7
// baseline (speedup 1.0000x reference)
#include <cuda_runtime.h>
#include <cuda_bf16.h>

#define SQL 2048
#define DMODEL 1024
#define NB 2
#define NH 16
#define HDIM 64

// Scratch (allocation-free rule: __device__ globals)
__device__ float g_qh[(size_t)NB * SQL * DMODEL];
__device__ float g_k [(size_t)NB * SQL * DMODEL];
__device__ float g_v [(size_t)NB * SQL * DMODEL];

// ---------------------------------------------------------------------------
// tf32 / cp.async helpers
// ---------------------------------------------------------------------------
__device__ __forceinline__ float f2tf32(float x) {
    unsigned u;
    asm("cvt.rna.tf32.f32 %0, %1;" : "=r"(u) : "f"(x));
    return __uint_as_float(u);
}

__device__ __forceinline__ void mma_tf32(
    float* c, const unsigned* a, const unsigned* b)
{
    asm volatile(
        "mma.sync.aligned.m16n8k8.row.col.f32.tf32.tf32.f32 "
        "{%0,%1,%2,%3}, {%4,%5,%6,%7}, {%8,%9}, {%0,%1,%2,%3};"
        : "+f"(c[0]), "+f"(c[1]), "+f"(c[2]), "+f"(c[3])
        : "r"(a[0]), "r"(a[1]), "r"(a[2]), "r"(a[3]),
          "r"(b[0]), "r"(b[1]));
}

__device__ __forceinline__ void cp16(unsigned smem_dst, const void* gsrc) {
    asm volatile("cp.async.cg.shared.global [%0], [%1], 16;\n"
                 :: "r"(smem_dst), "l"(gsrc));
}
#define CP_COMMIT() asm volatile("cp.async.commit_group;\n" ::: "memory")
#define CP_WAIT(n)  asm volatile("cp.async.wait_group %0;\n" :: "n"(n) : "memory")

// ---------------------------------------------------------------------------
// tf32 tensor-core GEMM, 128x128x16 tile, 8 warps (64x32 warp-tile each),
// double-buffered smem.  C = A[M,K] @ B[K,N].  If C1 != nullptr, cols >=
// halfN go to C1 (width halfN), else C0.  do_cvt: round outputs to tf32.
// ---------------------------------------------------------------------------
__global__ __launch_bounds__(256) void gemm_tc(
    const float* __restrict__ A, const float* __restrict__ Bm,
    float* __restrict__ C0, float* __restrict__ C1,
    int M, int N, int K, int halfN, int do_cvt)
{
    __shared__ float sA[2][128][20];
    __shared__ float sB[2][16][136];

    int t    = threadIdx.x;
    int lane = t & 31;
    int warp = t >> 5;
    int wm   = warp >> 2;
    int wn   = warp & 3;
    int brow = blockIdx.y * 128, bcol = blockIdx.x * 128;

    float acc[4][4][4];
    #pragma unroll
    for (int mi = 0; mi < 4; mi++)
        #pragma unroll
        for (int ni = 0; ni < 4; ni++)
            #pragma unroll
            for (int r = 0; r < 4; r++) acc[mi][ni][r] = 0.0f;

    const float* Ap0 = A + (size_t)(brow + (t >> 2)) * K + (t & 3) * 4;
    const float* Ap1 = Ap0 + (size_t)64 * K;
    const float* Bp0 = Bm + (size_t)(t >> 5) * N + bcol + (t & 31) * 4;
    const float* Bp1 = Bp0 + (size_t)8 * N;

    int arow = t >> 2,  acg = (t & 3) * 4;
    int bk   = t >> 5,  bcg = (t & 31) * 4;

    float4 a40 = *(const float4*)(Ap0);
    float4 a41 = *(const float4*)(Ap1);
    float4 b40 = *(const float4*)(Bp0);
    float4 b41 = *(const float4*)(Bp1);

    {
        float4 v;
        v = make_float4(f2tf32(a40.x), f2tf32(a40.y), f2tf32(a40.z), f2tf32(a40.w));
        *(float4*)&sA[0][arow][acg] = v;
        v = make_float4(f2tf32(a41.x), f2tf32(a41.y), f2tf32(a41.z), f2tf32(a41.w));
        *(float4*)&sA[0][arow + 64][acg] = v;
        v = make_float4(f2tf32(b40.x), f2tf32(b40.y), f2tf32(b40.z), f2tf32(b40.w));
        *(float4*)&sB[0][bk][bcg] = v;
        v = make_float4(f2tf32(b41.x), f2tf32(b41.y), f2tf32(b41.z), f2tf32(b41.w));
        *(float4*)&sB[0][bk + 8][bcg] = v;
    }
    __syncthreads();

    int buf = 0;
    for (int k0 = 0; k0 < K; k0 += 16, buf ^= 1) {
        bool has_next = (k0 + 16) < K;
        if (has_next) {
            a40 = *(const float4*)(Ap0 + (k0 + 16));
            a41 = *(const float4*)(Ap1 + (k0 + 16));
            b40 = *(const float4*)(Bp0 + (size_t)(k0 + 16) * N);
            b41 = *(const float4*)(Bp1 + (size_t)(k0 + 16) * N);
        }
        #pragma unroll
        for (int ks = 0; ks < 16; ks += 8) {
            unsigned af[4][4];
            #pragma unroll
            for (int mi = 0; mi < 4; mi++) {
                int r = wm * 64 + mi * 16 + (lane >> 2);
                int c = ks + (lane & 3);
                af[mi][0] = __float_as_uint(sA[buf][r][c]);
                af[mi][1] = __float_as_uint(sA[buf][r + 8][c]);
                af[mi][2] = __float_as_uint(sA[buf][r][c + 4]);
                af[mi][3] = __float_as_uint(sA[buf][r + 8][c + 4]);
            }
            unsigned bf[4][2];
            #pragma unroll
            for (int ni = 0; ni < 4; ni++) {
                int cb = wn * 32 + ni * 8 + (lane >> 2);
                int kr = ks + (lane & 3);
                bf[ni][0] = __float_as_uint(sB[buf][kr][cb]);
                bf[ni][1] = __float_as_uint(sB[buf][kr + 4][cb]);
            }
            #pragma unroll
            for (int mi = 0; mi < 4; mi++)
                #pragma unroll
                for (int ni = 0; ni < 4; ni++)
                    mma_tf32(acc[mi][ni], af[mi], bf[ni]);
        }
        if (has_next) {
            int nb = buf ^ 1;
            float4 v;
            v = make_float4(f2tf32(a40.x), f2tf32(a40.y), f2tf32(a40.z), f2tf32(a40.w));
            *(float4*)&sA[nb][arow][acg] = v;
            v = make_float4(f2tf32(a41.x), f2tf32(a41.y), f2tf32(a41.z), f2tf32(a41.w));
            *(float4*)&sA[nb][arow + 64][acg] = v;
            v = make_float4(f2tf32(b40.x), f2tf32(b40.y), f2tf32(b40.z), f2tf32(b40.w));
            *(float4*)&sB[nb][bk][bcg] = v;
            v = make_float4(f2tf32(b41.x), f2tf32(b41.y), f2tf32(b41.z), f2tf32(b41.w));
            *(float4*)&sB[nb][bk + 8][bcg] = v;
        }
        __syncthreads();
    }

    #pragma unroll
    for (int mi = 0; mi < 4; mi++) {
        #pragma unroll
        for (int ni = 0; ni < 4; ni++) {
            int row = brow + wm * 64 + mi * 16 + (lane >> 2);
            int col = bcol + wn * 32 + ni * 8 + 2 * (lane & 3);
            float* dst;
            int ccol = col;
            if (C1 && col >= halfN) { dst = C1; ccol = col - halfN; }
            else                    { dst = C0; }
            float v0 = acc[mi][ni][0], v1 = acc[mi][ni][1];
            float v2 = acc[mi][ni][2], v3 = acc[mi][ni][3];
            if (do_cvt) { v0 = f2tf32(v0); v1 = f2tf32(v1);
                          v2 = f2tf32(v2); v3 = f2tf32(v3); }
            *(float2*)(dst + (size_t)row * halfN + ccol) = make_float2(v0, v1);
            *(float2*)(dst + (size_t)(row + 8) * halfN + ccol) = make_float2(v2, v3);
        }
    }
}

// ---------------------------------------------------------------------------
// LayerNorm over last dim (64) per head.  One warp per row; tf32 output.
// ---------------------------------------------------------------------------
__global__ __launch_bounds__(256) void ln64(
    float* __restrict__ v, const float* __restrict__ gamma,
    const float* __restrict__ beta)
{
    int lane = threadIdx.x & 31;
    size_t row = (size_t)blockIdx.x * (blockDim.x >> 5) + (threadIdx.x >> 5);
    float* p = v + row * HDIM;
    float x0 = p[lane], x1 = p[lane + 32];
    float s  = x0 + x1;
    float ss = x0 * x0 + x1 * x1;
    #pragma unroll
    for (int o = 16; o > 0; o >>= 1) {
        s  += __shfl_xor_sync(0xffffffffu, s,  o);
        ss += __shfl_xor_sync(0xffffffffu, ss, o);
    }
    float mu  = s * (1.0f / HDIM);
    float var = ss * (1.0f / HDIM) - mu * mu;
    float r   = rsqrtf(var + 1e-5f);
    p[lane]      = f2tf32((x0 - mu) * r * gamma[lane]      + beta[lane]);
    p[lane + 32] = f2tf32((x1 - mu) * r * gamma[lane + 32] + beta[lane + 32]);
}

// ---------------------------------------------------------------------------
// Tensor-core flash sigmoid attention v4 (tf32 mma).
// 256 threads / 8 warps; warp w owns q-rows 16w..16w+15 and the FULL
// 64-wide n (S) and d (O) range -> P is warp-private (smem scratch with
// __syncwarp only; no CTA barrier for the P round-trip).
// ONE __syncthreads per kv tile (K/V double-buffer protection).
// Inputs qh/k/v are already tf32-rounded in gmem.
// Smem (104 KB -> 2 CTAs/SM):
//   sP [128][68] : Q staging (prologue), then per-warp P scratch
//   sK [2][64][68], sV [2][64][72] : K/V double buffers
// ---------------------------------------------------------------------------
__global__ __launch_bounds__(256, 2) void attn_tc(
    const float* __restrict__ qh, const float* __restrict__ kb,
    const float* __restrict__ vb, float* __restrict__ out)
{
    extern __shared__ float sm[];
    float* sP = sm;                          // 128*68 = 8704 floats
    float* sK = sP + 128 * 68;               // 2 * 64*68
    float* sV = sK + 2 * 64 * 68;            // 2 * 64*72

    const int t = threadIdx.x, lane = t & 31, warp = t >> 5;
    const int qb = blockIdx.x, hd = blockIdx.y, b = blockIdx.z;
    const int q0 = qb * 128;

    const float* Qb = qh + ((size_t)(b * SQL + q0)) * DMODEL + hd * HDIM;
    const float* Kb = kb + ((size_t)b * SQL) * DMODEL + hd * HDIM;
    const float* Vb = vb + ((size_t)b * SQL) * DMODEL + hd * HDIM;

    unsigned sPa = (unsigned)__cvta_generic_to_shared(sP);
    unsigned sKa = (unsigned)__cvta_generic_to_shared(sK);
    unsigned sVa = (unsigned)__cvta_generic_to_shared(sV);

    // ---- stage Q via cp.async into sP (warp w stages its own 16 rows) ----
    {
        int r = t >> 1;                    // rows 16w..16w+15 for warp w
        int cgB = (t & 1) * 128;           // byte offset in 256B row
        const char* src = (const char*)(Qb + (size_t)r * DMODEL) + cgB;
        unsigned dst = sPa + r * 272 + cgB;
        #pragma unroll
        for (int i = 0; i < 8; i++) cp16(dst + i * 16, src + i * 16);
    }
    CP_COMMIT();                           // group: Q

    // ---- stage K/V tile 0 ----
    const int kr_ = t >> 2;                // 0..63
    const int kcB = (t & 3) * 64;          // byte offset in 256B row
    {
        const char* ks = (const char*)(Kb + (size_t)kr_ * DMODEL) + kcB;
        const char* vs = (const char*)(Vb + (size_t)kr_ * DMODEL) + kcB;
        unsigned kd = sKa + kr_ * 272 + kcB;
        unsigned vd = sVa + kr_ * 288 + kcB;
        #pragma unroll
        for (int i = 0; i < 4; i++) { cp16(kd + i * 16, ks + i * 16);
                                      cp16(vd + i * 16, vs + i * 16); }
    }
    CP_COMMIT();                           // group: KV0

    CP_WAIT(1);                            // Q arrived (KV0 may be pending)
    __syncwarp();

    // ---- persistent Q A-fragments (warp-private rows) ----
    unsigned qf[8][4];
    {
        int r = warp * 16 + (lane >> 2);
        #pragma unroll
        for (int kk = 0; kk < 8; kk++) {
            int c = kk * 8 + (lane & 3);
            qf[kk][0] = __float_as_uint(sP[r * 68 + c]);
            qf[kk][1] = __float_as_uint(sP[(r + 8) * 68 + c]);
            qf[kk][2] = __float_as_uint(sP[r * 68 + c + 4]);
            qf[kk][3] = __float_as_uint(sP[(r + 8) * 68 + c + 4]);
        }
    }
    __syncwarp();                          // qf reads done before P overwrite

    float oacc[8][4];
    #pragma unroll
    for (int ni = 0; ni < 8; ni++)
        #pragma unroll
        for (int r = 0; r < 4; r++) oacc[ni][r] = 0.0f;

    const int jmax = 2 * qb + 1;
    const int pr  = warp * 16 + (lane >> 2);   // this lane's P row

    for (int j = 0; j <= jmax; j++) {
        CP_WAIT(0);                        // tile j fully arrived
        __syncthreads();                   // visible to all; buf^1 readers done
        if (j < jmax) {                    // issue tile j+1 into buf^1
            int k0n = (j + 1) * 64;
            const char* ks = (const char*)(Kb + (size_t)(k0n + kr_) * DMODEL) + kcB;
            const char* vs = (const char*)(Vb + (size_t)(k0n + kr_) * DMODEL) + kcB;
            unsigned kd = sKa + ((j + 1) & 1) * 17408 + kr_ * 272 + kcB;
            unsigned vd = sVa + ((j + 1) & 1) * 18432 + kr_ * 288 + kcB;
            #pragma unroll
            for (int i = 0; i < 4; i++) { cp16(kd + i * 16, ks + i * 16);
                                          cp16(vd + i * 16, vs + i * 16); }
            CP_COMMIT();
        }

        const float* bK = sK + (j & 1) * (64 * 68);
        const float* bV = sV + (j & 1) * (64 * 72);

        // ---- S = Q K^T (full 64-wide), two ni-halves to cap registers ----
        #pragma unroll
        for (int half = 0; half < 2; half++) {
            float sfr[4][4];
            #pragma unroll
            for (int ni = 0; ni < 4; ni++)
                #pragma unroll
                for (int r = 0; r < 4; r++) sfr[ni][r] = 0.0f;
            #pragma unroll
            for (int kk = 0; kk < 8; kk++) {
                #pragma unroll
                for (int ni = 0; ni < 4; ni++) {
                    int cb = half * 32 + ni * 8 + (lane >> 2);
                    int kr = kk * 8 + (lane & 3);
                    unsigned bbf[2];
                    bbf[0] = __float_as_uint(bK[cb * 68 + kr]);
                    bbf[1] = __float_as_uint(bK[cb * 68 + kr + 4]);
                    mma_tf32(sfr[ni], qf[kk], bbf);
                }
            }
            // sigmoid + causal mask -> P (tf32) into warp-private sP rows
            int g0 = q0 + pr, g1 = g0 + 8;
            #pragma unroll
            for (int ni = 0; ni < 4; ni++) {
                int c  = half * 32 + ni * 8 + 2 * (lane & 3);
                int gc = j * 64 + c;
                float p00 = __fdividef(1.f, 1.f + __expf(8.f - sfr[ni][0] * 0.125f));
                float p01 = __fdividef(1.f, 1.f + __expf(8.f - sfr[ni][1] * 0.125f));
                float p10 = __fdividef(1.f, 1.f + __expf(8.f - sfr[ni][2] * 0.125f));
                float p11 = __fdividef(1.f, 1.f + __expf(8.f - sfr[ni][3] * 0.125f));
                p00 = (gc     <= g0) ? p00 : 0.f;
                p01 = (gc + 1 <= g0) ? p01 : 0.f;
                p10 = (gc     <= g1) ? p10 : 0.f;
                p11 = (gc + 1 <= g1) ? p11 : 0.f;
                *(float2*)&sP[pr * 68 + c] =
                    make_float2(f2tf32(p00), f2tf32(p01));
                *(float2*)&sP[(pr + 8) * 68 + c] =
                    make_float2(f2tf32(p10), f2tf32(p11));
            }
        }
        __syncwarp();                      // P visible within warp

        // ---- O += P V (full 64-wide d) ----
        #pragma unroll
        for (int kk = 0; kk < 8; kk++) {
            int c = kk * 8 + (lane & 3);
            unsigned pf[4];
            pf[0] = __float_as_uint(sP[pr * 68 + c]);
            pf[1] = __float_as_uint(sP[(pr + 8) * 68 + c]);
            pf[2] = __float_as_uint(sP[pr * 68 + c + 4]);
            pf[3] = __float_as_uint(sP[(pr + 8) * 68 + c + 4]);
            #pragma unroll
            for (int ni = 0; ni < 8; ni++) {
                int cb = ni * 8 + (lane >> 2);
                int kr = kk * 8 + (lane & 3);
                unsigned bbf[2];
                bbf[0] = __float_as_uint(bV[kr * 72 + cb]);
                bbf[1] = __float_as_uint(bV[(kr + 4) * 72 + cb]);
                mma_tf32(oacc[ni], pf, bbf);
            }
        }
    }

    // ---- epilogue ----
    {
        float* ob = out + ((size_t)(b * SQL + q0 + pr)) * DMODEL + hd * HDIM;
        #pragma unroll
        for (int ni = 0; ni < 8; ni++) {
            int c = ni * 8 + 2 * (lane & 3);
            *(float2*)(ob + c) = make_float2(oacc[ni][0], oacc[ni][1]);
            *(float2*)(ob + (size_t)8 * DMODEL + c) =
                make_float2(oacc[ni][2], oacc[ni][3]);
        }
    }
}

#define ATTN_SMEM ((128 * 68 + 2 * 64 * 68 + 2 * 64 * 72) * 4)   // 106496 B

// ---------------------------------------------------------------------------
extern "C" void kernel_launch(void* const* d_in, const int* in_sizes, int n_in,
                              void* d_out, int out_size)
{
    const float* q     = (const float*)d_in[0];
    const float* kv    = (const float*)d_in[1];
    const float* Wq    = (const float*)d_in[2];
    const float* Wkv   = (const float*)d_in[3];
    const float* gamma = (const float*)d_in[4];
    const float* beta  = (const float*)d_in[5];
    const float* Wproj = (const float*)d_in[6];
    float* out = (float*)d_out;

    float *qh, *kbuf, *vbuf;
    cudaGetSymbolAddress((void**)&qh,   g_qh);
    cudaGetSymbolAddress((void**)&kbuf, g_k);
    cudaGetSymbolAddress((void**)&vbuf, g_v);

    cudaFuncSetAttribute(attn_tc,
        cudaFuncAttributeMaxDynamicSharedMemorySize, ATTN_SMEM);

    const int M = NB * SQL;   // 4096

    // 1) qh = q @ Wq  (tf32-rounded output)
    gemm_tc<<<dim3(DMODEL / 128, M / 128), 256>>>(
        q, Wq, qh, nullptr, M, DMODEL, DMODEL, DMODEL, 1);

    // 2) kvh = kv @ Wkv, split K / V (tf32-rounded)
    gemm_tc<<<dim3(2 * DMODEL / 128, M / 128), 256>>>(
        kv, Wkv, kbuf, vbuf, M, 2 * DMODEL, DMODEL, DMODEL, 1);

    // 3) per-head LayerNorm of V (writes tf32)
    ln64<<<(NB * SQL * NH) / 8, 256>>>(vbuf, gamma, beta);

    // 4) attention -> attn_times_v (first half of d_out, fp32)
    attn_tc<<<dim3(SQL / 128, NH, NB), 256, ATTN_SMEM>>>(qh, kbuf, vbuf, out);

    // 5) attn_proj = attn_times_v @ Wproj (second half of d_out, fp32)
    gemm_tc<<<dim3(DMODEL / 128, M / 128), 256>>>(
        out, Wproj, out + (size_t)M * DMODEL, nullptr, M, DMODEL, DMODEL, DMODEL, 0);
}

// round 8
// speedup vs baseline: 1.0525x; 1.0525x over previous
#include <cuda_runtime.h>
#include <cuda_bf16.h>

#define SQL 2048
#define DMODEL 1024
#define NB 2
#define NH 16
#define HDIM 64

// Scratch (allocation-free rule: __device__ globals)
__device__ float g_qh[(size_t)NB * SQL * DMODEL];
__device__ float g_k [(size_t)NB * SQL * DMODEL];
__device__ float g_v [(size_t)NB * SQL * DMODEL];
__device__ float g_vt[(size_t)NB * NH * HDIM * SQL];   // V^T per head: [b][h][d][skv]

// ---------------------------------------------------------------------------
// tf32 / cp.async / ldmatrix helpers
// ---------------------------------------------------------------------------
__device__ __forceinline__ float f2tf32(float x) {
    unsigned u;
    asm("cvt.rna.tf32.f32 %0, %1;" : "=r"(u) : "f"(x));
    return __uint_as_float(u);
}

__device__ __forceinline__ void mma_tf32(
    float* c, const unsigned* a, const unsigned* b)
{
    asm volatile(
        "mma.sync.aligned.m16n8k8.row.col.f32.tf32.tf32.f32 "
        "{%0,%1,%2,%3}, {%4,%5,%6,%7}, {%8,%9}, {%0,%1,%2,%3};"
        : "+f"(c[0]), "+f"(c[1]), "+f"(c[2]), "+f"(c[3])
        : "r"(a[0]), "r"(a[1]), "r"(a[2]), "r"(a[3]),
          "r"(b[0]), "r"(b[1]));
}

__device__ __forceinline__ void ldsm4(
    unsigned& r0, unsigned& r1, unsigned& r2, unsigned& r3, unsigned addr)
{
    asm volatile(
        "ldmatrix.sync.aligned.m8n8.x4.shared.b16 {%0,%1,%2,%3}, [%4];"
        : "=r"(r0), "=r"(r1), "=r"(r2), "=r"(r3) : "r"(addr));
}

__device__ __forceinline__ void cp16(unsigned smem_dst, const void* gsrc) {
    asm volatile("cp.async.cg.shared.global [%0], [%1], 16;\n"
                 :: "r"(smem_dst), "l"(gsrc));
}
#define CP_COMMIT() asm volatile("cp.async.commit_group;\n" ::: "memory")
#define CP_WAIT(n)  asm volatile("cp.async.wait_group %0;\n" :: "n"(n) : "memory")

// ---------------------------------------------------------------------------
// tf32 tensor-core GEMM, 128x128x16 tile, 8 warps, double-buffered smem.
// C = A[M,K] @ B[K,N].  If C1 != nullptr, cols >= halfN go to C1.
// do_cvt: round outputs to tf32.
// ---------------------------------------------------------------------------
__global__ __launch_bounds__(256) void gemm_tc(
    const float* __restrict__ A, const float* __restrict__ Bm,
    float* __restrict__ C0, float* __restrict__ C1,
    int M, int N, int K, int halfN, int do_cvt)
{
    __shared__ float sA[2][128][20];
    __shared__ float sB[2][16][136];

    int t    = threadIdx.x;
    int lane = t & 31;
    int warp = t >> 5;
    int wm   = warp >> 2;
    int wn   = warp & 3;
    int brow = blockIdx.y * 128, bcol = blockIdx.x * 128;

    float acc[4][4][4];
    #pragma unroll
    for (int mi = 0; mi < 4; mi++)
        #pragma unroll
        for (int ni = 0; ni < 4; ni++)
            #pragma unroll
            for (int r = 0; r < 4; r++) acc[mi][ni][r] = 0.0f;

    const float* Ap0 = A + (size_t)(brow + (t >> 2)) * K + (t & 3) * 4;
    const float* Ap1 = Ap0 + (size_t)64 * K;
    const float* Bp0 = Bm + (size_t)(t >> 5) * N + bcol + (t & 31) * 4;
    const float* Bp1 = Bp0 + (size_t)8 * N;

    int arow = t >> 2,  acg = (t & 3) * 4;
    int bk   = t >> 5,  bcg = (t & 31) * 4;

    float4 a40 = *(const float4*)(Ap0);
    float4 a41 = *(const float4*)(Ap1);
    float4 b40 = *(const float4*)(Bp0);
    float4 b41 = *(const float4*)(Bp1);

    {
        float4 v;
        v = make_float4(f2tf32(a40.x), f2tf32(a40.y), f2tf32(a40.z), f2tf32(a40.w));
        *(float4*)&sA[0][arow][acg] = v;
        v = make_float4(f2tf32(a41.x), f2tf32(a41.y), f2tf32(a41.z), f2tf32(a41.w));
        *(float4*)&sA[0][arow + 64][acg] = v;
        v = make_float4(f2tf32(b40.x), f2tf32(b40.y), f2tf32(b40.z), f2tf32(b40.w));
        *(float4*)&sB[0][bk][bcg] = v;
        v = make_float4(f2tf32(b41.x), f2tf32(b41.y), f2tf32(b41.z), f2tf32(b41.w));
        *(float4*)&sB[0][bk + 8][bcg] = v;
    }
    __syncthreads();

    int buf = 0;
    for (int k0 = 0; k0 < K; k0 += 16, buf ^= 1) {
        bool has_next = (k0 + 16) < K;
        if (has_next) {
            a40 = *(const float4*)(Ap0 + (k0 + 16));
            a41 = *(const float4*)(Ap1 + (k0 + 16));
            b40 = *(const float4*)(Bp0 + (size_t)(k0 + 16) * N);
            b41 = *(const float4*)(Bp1 + (size_t)(k0 + 16) * N);
        }
        #pragma unroll
        for (int ks = 0; ks < 16; ks += 8) {
            unsigned af[4][4];
            #pragma unroll
            for (int mi = 0; mi < 4; mi++) {
                int r = wm * 64 + mi * 16 + (lane >> 2);
                int c = ks + (lane & 3);
                af[mi][0] = __float_as_uint(sA[buf][r][c]);
                af[mi][1] = __float_as_uint(sA[buf][r + 8][c]);
                af[mi][2] = __float_as_uint(sA[buf][r][c + 4]);
                af[mi][3] = __float_as_uint(sA[buf][r + 8][c + 4]);
            }
            unsigned bf[4][2];
            #pragma unroll
            for (int ni = 0; ni < 4; ni++) {
                int cb = wn * 32 + ni * 8 + (lane >> 2);
                int kr = ks + (lane & 3);
                bf[ni][0] = __float_as_uint(sB[buf][kr][cb]);
                bf[ni][1] = __float_as_uint(sB[buf][kr + 4][cb]);
            }
            #pragma unroll
            for (int mi = 0; mi < 4; mi++)
                #pragma unroll
                for (int ni = 0; ni < 4; ni++)
                    mma_tf32(acc[mi][ni], af[mi], bf[ni]);
        }
        if (has_next) {
            int nb = buf ^ 1;
            float4 v;
            v = make_float4(f2tf32(a40.x), f2tf32(a40.y), f2tf32(a40.z), f2tf32(a40.w));
            *(float4*)&sA[nb][arow][acg] = v;
            v = make_float4(f2tf32(a41.x), f2tf32(a41.y), f2tf32(a41.z), f2tf32(a41.w));
            *(float4*)&sA[nb][arow + 64][acg] = v;
            v = make_float4(f2tf32(b40.x), f2tf32(b40.y), f2tf32(b40.z), f2tf32(b40.w));
            *(float4*)&sB[nb][bk][bcg] = v;
            v = make_float4(f2tf32(b41.x), f2tf32(b41.y), f2tf32(b41.z), f2tf32(b41.w));
            *(float4*)&sB[nb][bk + 8][bcg] = v;
        }
        __syncthreads();
    }

    #pragma unroll
    for (int mi = 0; mi < 4; mi++) {
        #pragma unroll
        for (int ni = 0; ni < 4; ni++) {
            int row = brow + wm * 64 + mi * 16 + (lane >> 2);
            int col = bcol + wn * 32 + ni * 8 + 2 * (lane & 3);
            float* dst;
            int ccol = col;
            if (C1 && col >= halfN) { dst = C1; ccol = col - halfN; }
            else                    { dst = C0; }
            float v0 = acc[mi][ni][0], v1 = acc[mi][ni][1];
            float v2 = acc[mi][ni][2], v3 = acc[mi][ni][3];
            if (do_cvt) { v0 = f2tf32(v0); v1 = f2tf32(v1);
                          v2 = f2tf32(v2); v3 = f2tf32(v3); }
            *(float2*)(dst + (size_t)row * halfN + ccol) = make_float2(v0, v1);
            *(float2*)(dst + (size_t)(row + 8) * halfN + ccol) = make_float2(v2, v3);
        }
    }
}

// ---------------------------------------------------------------------------
// LayerNorm (per-head, dim 64) + transpose.  Block handles 64 seq positions
// of one (b, h): warp w does rows 8w..8w+7 (one warp per row at a time),
// stages results in smem [d][s], then writes V^T coalesced to g_vt.
// Output rounded to tf32 (consumed only by tf32 attention mma).
// ---------------------------------------------------------------------------
__global__ __launch_bounds__(256) void ln64t(
    const float* __restrict__ v, const float* __restrict__ gamma,
    const float* __restrict__ beta, float* __restrict__ vt)
{
    __shared__ float sT[64 * 68];        // [d][s_local], pad 68

    int t = threadIdx.x, lane = t & 31, warp = t >> 5;
    int s0 = blockIdx.x * 64, h = blockIdx.y, b = blockIdx.z;

    float g0 = gamma[lane], g1 = gamma[lane + 32];
    float be0 = beta[lane], be1 = beta[lane + 32];

    #pragma unroll
    for (int i = 0; i < 8; i++) {
        int sl = warp * 8 + i;
        const float* p = v + ((size_t)(b * SQL + s0 + sl)) * DMODEL + h * HDIM;
        float x0 = p[lane], x1 = p[lane + 32];
        float s  = x0 + x1;
        float ss = x0 * x0 + x1 * x1;
        #pragma unroll
        for (int o = 16; o > 0; o >>= 1) {
            s  += __shfl_xor_sync(0xffffffffu, s,  o);
            ss += __shfl_xor_sync(0xffffffffu, ss, o);
        }
        float mu  = s * (1.0f / HDIM);
        float var = ss * (1.0f / HDIM) - mu * mu;
        float r   = rsqrtf(var + 1e-5f);
        sT[lane * 68 + sl]        = f2tf32((x0 - mu) * r * g0 + be0);
        sT[(lane + 32) * 68 + sl] = f2tf32((x1 - mu) * r * g1 + be1);
    }
    __syncthreads();

    int d = t >> 2, cg = (t & 3) * 16;
    float* ob = vt + ((size_t)(b * NH + h) * HDIM + d) * SQL + s0 + cg;
    #pragma unroll
    for (int i = 0; i < 4; i++)
        *(float4*)(ob + i * 4) = *(const float4*)&sT[d * 68 + cg + i * 4];
}

// ---------------------------------------------------------------------------
// Tensor-core flash sigmoid attention v5 (tf32 mma + ldmatrix).
// 256 threads / 8 warps; warp w owns q-rows 16w..16w+15 and the full 64-wide
// n/d range.  All fragment loads via ldmatrix.x4 (tf32 == b32 tiles; the
// m8n8.b16 thread map (row=lane>>2, col32=lane&3) matches tf32 fragments).
// V comes pre-transposed from g_vt so its B-frags are ldmatrix-ready.
// Warp-level causal tile skip: warp w skips tile j if 64j > q0+16w+15.
// Smem 104448 B -> 2 CTAs/SM:
//   sP [128][68] : Q staging, then per-warp P scratch
//   sK [2][64][68] : K tiles [kv][d]
//   sV [2][64][68] : V^T tiles [d][kv]
// ---------------------------------------------------------------------------
__global__ __launch_bounds__(256, 2) void attn_tc(
    const float* __restrict__ qh, const float* __restrict__ kb,
    const float* __restrict__ vt, float* __restrict__ out)
{
    extern __shared__ float sm[];
    float* sP = sm;                          // 128*68
    float* sK = sP + 128 * 68;               // 2*64*68
    float* sV = sK + 2 * 64 * 68;            // 2*64*68

    const int t = threadIdx.x, lane = t & 31, warp = t >> 5;
    const int qb = blockIdx.x, hd = blockIdx.y, b = blockIdx.z;
    const int q0 = qb * 128;

    const float* Qb  = qh + ((size_t)(b * SQL + q0)) * DMODEL + hd * HDIM;
    const float* Kb  = kb + ((size_t)b * SQL) * DMODEL + hd * HDIM;
    const float* Vtb = vt + ((size_t)(b * NH + hd) * HDIM) * SQL;

    unsigned sPa = (unsigned)__cvta_generic_to_shared(sP);
    unsigned sKa = (unsigned)__cvta_generic_to_shared(sK);
    unsigned sVa = (unsigned)__cvta_generic_to_shared(sV);

    // ---- stage Q (warp-local rows) ----
    {
        int r = t >> 1;
        int cgB = (t & 1) * 128;
        const char* src = (const char*)(Qb + (size_t)r * DMODEL) + cgB;
        unsigned dst = sPa + r * 272 + cgB;
        #pragma unroll
        for (int i = 0; i < 8; i++) cp16(dst + i * 16, src + i * 16);
    }
    CP_COMMIT();                             // group: Q

    // ---- stage K / V^T tile 0 ----
    const int kr_ = t >> 2;                  // K: kv row / V^T: d row (0..63)
    const int kcB = (t & 3) * 64;            // byte offset within 256B row
    {
        const char* ks = (const char*)(Kb + (size_t)kr_ * DMODEL) + kcB;
        const char* vs = (const char*)(Vtb + (size_t)kr_ * SQL) + kcB;
        unsigned kd = sKa + kr_ * 272 + kcB;
        unsigned vd = sVa + kr_ * 272 + kcB;
        #pragma unroll
        for (int i = 0; i < 4; i++) { cp16(kd + i * 16, ks + i * 16);
                                      cp16(vd + i * 16, vs + i * 16); }
    }
    CP_COMMIT();                             // group: KV0

    CP_WAIT(1);                              // Q arrived
    __syncwarp();

    // ---- ldmatrix per-thread byte offsets ----
    // B-type tiles (K, V^T): x4 order = (n-lo,k-lo),(n-lo,k-hi),(n+8,k-lo),(n+8,k-hi)
    const unsigned nb8   = (lane & 7) + ((lane >> 4) << 3);
    const unsigned kb4   = ((lane >> 3) & 1) << 2;
    const unsigned boffB = (nb8 * 68 + kb4) * 4;
    // A-type tiles (Q, P): x4 order = (m-lo,k-lo),(m-hi,k-lo),(m-lo,k-hi),(m-hi,k-hi)
    const unsigned arow  = (((lane >> 3) & 1) << 3) + (lane & 7);
    const unsigned akb   = (lane >> 4) << 2;
    const unsigned boffA = ((warp * 16 + arow) * 68 + akb) * 4;

    // ---- persistent Q A-fragments via ldmatrix ----
    unsigned qf[8][4];
    #pragma unroll
    for (int kk = 0; kk < 8; kk++)
        ldsm4(qf[kk][0], qf[kk][1], qf[kk][2], qf[kk][3], sPa + boffA + kk * 32);
    __syncwarp();                            // qf done before P overwrites sP

    float oacc[8][4];
    #pragma unroll
    for (int ni = 0; ni < 8; ni++)
        #pragma unroll
        for (int r = 0; r < 4; r++) oacc[ni][r] = 0.0f;

    const int jmax = 2 * qb + 1;
    const int pr   = warp * 16 + (lane >> 2);
    const int qlim = q0 + warp * 16 + 15;    // max q row of this warp

    for (int j = 0; j <= jmax; j++) {
        CP_WAIT(0);                          // tile j fully arrived
        __syncthreads();
        if (j < jmax) {                      // prefetch tile j+1 into buf^1
            int k0n = (j + 1) * 64;
            const char* ks = (const char*)(Kb + (size_t)(k0n + kr_) * DMODEL) + kcB;
            const char* vs = (const char*)(Vtb + (size_t)kr_ * SQL + k0n) + kcB;
            unsigned kd = sKa + ((j + 1) & 1) * 17408 + kr_ * 272 + kcB;
            unsigned vd = sVa + ((j + 1) & 1) * 17408 + kr_ * 272 + kcB;
            #pragma unroll
            for (int i = 0; i < 4; i++) { cp16(kd + i * 16, ks + i * 16);
                                          cp16(vd + i * 16, vs + i * 16); }
            CP_COMMIT();
        }

        if (64 * j <= qlim) {                // warp-level causal tile skip
            unsigned kbase = sKa + (j & 1) * 17408;
            unsigned vbase = sVa + (j & 1) * 17408;

            // ---- S = Q K^T, two 32-wide n-halves (register cap) ----
            #pragma unroll
            for (int half = 0; half < 2; half++) {
                float sfr[4][4];
                #pragma unroll
                for (int ni = 0; ni < 4; ni++)
                    #pragma unroll
                    for (int r = 0; r < 4; r++) sfr[ni][r] = 0.0f;
                #pragma unroll
                for (int kk = 0; kk < 8; kk++) {
                    #pragma unroll
                    for (int nip = 0; nip < 2; nip++) {
                        int np = half * 2 + nip;
                        unsigned b0, b1, b2, b3;
                        ldsm4(b0, b1, b2, b3,
                              kbase + np * 4352 + kk * 32 + boffB);
                        unsigned bl[2] = { b0, b1 }, bh[2] = { b2, b3 };
                        mma_tf32(sfr[nip * 2 + 0], qf[kk], bl);
                        mma_tf32(sfr[nip * 2 + 1], qf[kk], bh);
                    }
                }
                // ---- sigmoid + causal mask -> P (tf32) into sP ----
                int g0 = q0 + pr, g1 = g0 + 8;
                #pragma unroll
                for (int n4 = 0; n4 < 4; n4++) {
                    int ni = half * 4 + n4;
                    int c  = ni * 8 + 2 * (lane & 3);
                    int gc = j * 64 + c;
                    // sigmoid(0.125*s - 8) = 1/(1+exp2(11.5415603 - 0.18033688*s))
                    float e0 = exp2f(fmaf(sfr[n4][0], -0.18033688f, 11.5415603f));
                    float e1 = exp2f(fmaf(sfr[n4][1], -0.18033688f, 11.5415603f));
                    float e2 = exp2f(fmaf(sfr[n4][2], -0.18033688f, 11.5415603f));
                    float e3 = exp2f(fmaf(sfr[n4][3], -0.18033688f, 11.5415603f));
                    float p00 = __fdividef(1.f, 1.f + e0);
                    float p01 = __fdividef(1.f, 1.f + e1);
                    float p10 = __fdividef(1.f, 1.f + e2);
                    float p11 = __fdividef(1.f, 1.f + e3);
                    p00 = (gc     <= g0) ? p00 : 0.f;
                    p01 = (gc + 1 <= g0) ? p01 : 0.f;
                    p10 = (gc     <= g1) ? p10 : 0.f;
                    p11 = (gc + 1 <= g1) ? p11 : 0.f;
                    *(float2*)&sP[pr * 68 + c] =
                        make_float2(f2tf32(p00), f2tf32(p01));
                    *(float2*)&sP[(pr + 8) * 68 + c] =
                        make_float2(f2tf32(p10), f2tf32(p11));
                }
            }
            __syncwarp();                    // P visible within warp

            // ---- O += P V (ldmatrix for P and V^T) ----
            #pragma unroll
            for (int kk = 0; kk < 8; kk++) {
                unsigned pf[4];
                ldsm4(pf[0], pf[1], pf[2], pf[3], sPa + boffA + kk * 32);
                #pragma unroll
                for (int np = 0; np < 4; np++) {
                    unsigned b0, b1, b2, b3;
                    ldsm4(b0, b1, b2, b3,
                          vbase + np * 4352 + kk * 32 + boffB);
                    unsigned bl[2] = { b0, b1 }, bh[2] = { b2, b3 };
                    mma_tf32(oacc[np * 2 + 0], pf, bl);
                    mma_tf32(oacc[np * 2 + 1], pf, bh);
                }
            }
        }
    }

    // ---- epilogue ----
    {
        float* ob = out + ((size_t)(b * SQL + q0 + pr)) * DMODEL + hd * HDIM;
        #pragma unroll
        for (int ni = 0; ni < 8; ni++) {
            int c = ni * 8 + 2 * (lane & 3);
            *(float2*)(ob + c) = make_float2(oacc[ni][0], oacc[ni][1]);
            *(float2*)(ob + (size_t)8 * DMODEL + c) =
                make_float2(oacc[ni][2], oacc[ni][3]);
        }
    }
}

#define ATTN_SMEM ((128 * 68 + 2 * 64 * 68 + 2 * 64 * 68) * 4)   // 104448 B

// ---------------------------------------------------------------------------
extern "C" void kernel_launch(void* const* d_in, const int* in_sizes, int n_in,
                              void* d_out, int out_size)
{
    const float* q     = (const float*)d_in[0];
    const float* kv    = (const float*)d_in[1];
    const float* Wq    = (const float*)d_in[2];
    const float* Wkv   = (const float*)d_in[3];
    const float* gamma = (const float*)d_in[4];
    const float* beta  = (const float*)d_in[5];
    const float* Wproj = (const float*)d_in[6];
    float* out = (float*)d_out;

    float *qh, *kbuf, *vbuf, *vtbuf;
    cudaGetSymbolAddress((void**)&qh,    g_qh);
    cudaGetSymbolAddress((void**)&kbuf,  g_k);
    cudaGetSymbolAddress((void**)&vbuf,  g_v);
    cudaGetSymbolAddress((void**)&vtbuf, g_vt);

    cudaFuncSetAttribute(attn_tc,
        cudaFuncAttributeMaxDynamicSharedMemorySize, ATTN_SMEM);

    const int M = NB * SQL;   // 4096

    // 1) qh = q @ Wq  (tf32-rounded output)
    gemm_tc<<<dim3(DMODEL / 128, M / 128), 256>>>(
        q, Wq, qh, nullptr, M, DMODEL, DMODEL, DMODEL, 1);

    // 2) kvh = kv @ Wkv, split K / V (tf32-rounded)
    gemm_tc<<<dim3(2 * DMODEL / 128, M / 128), 256>>>(
        kv, Wkv, kbuf, vbuf, M, 2 * DMODEL, DMODEL, DMODEL, 1);

    // 3) per-head LayerNorm of V + transpose into g_vt (tf32)
    ln64t<<<dim3(SQL / 64, NH, NB), 256>>>(vbuf, gamma, beta, vtbuf);

    // 4) attention -> attn_times_v (first half of d_out, fp32)
    attn_tc<<<dim3(SQL / 128, NH, NB), 256, ATTN_SMEM>>>(qh, kbuf, vtbuf, out);

    // 5) attn_proj = attn_times_v @ Wproj (second half of d_out, fp32)
    gemm_tc<<<dim3(DMODEL / 128, M / 128), 256>>>(
        out, Wproj, out + (size_t)M * DMODEL, nullptr, M, DMODEL, DMODEL, DMODEL, 0);
}

// round 9
// speedup vs baseline: 1.0821x; 1.0281x over previous
#include <cuda_runtime.h>
#include <cuda_bf16.h>

#define SQL 2048
#define DMODEL 1024
#define NB 2
#define NH 16
#define HDIM 64

// Scratch (allocation-free rule: __device__ globals)
__device__ float g_qh [(size_t)NB * SQL * DMODEL];
__device__ float g_k  [(size_t)NB * SQL * DMODEL];
__device__ float g_v  [(size_t)NB * SQL * DMODEL];
__device__ float g_vt [(size_t)NB * NH * HDIM * SQL];   // V^T per head
__device__ float g_qc [(size_t)NB * SQL * DMODEL];      // tf32(q); later tf32(attn_out)
__device__ float g_kvc[(size_t)NB * SQL * DMODEL];      // tf32(kv)
__device__ float g_w  [(size_t)4 * DMODEL * DMODEL];    // tf32 W: [Wq | Wkv(2M) | Wproj]

// ---------------------------------------------------------------------------
// tf32 / cp.async / ldmatrix helpers
// ---------------------------------------------------------------------------
__device__ __forceinline__ float f2tf32(float x) {
    unsigned u;
    asm("cvt.rna.tf32.f32 %0, %1;" : "=r"(u) : "f"(x));
    return __uint_as_float(u);
}

__device__ __forceinline__ void mma_tf32(
    float* c, const unsigned* a, const unsigned* b)
{
    asm volatile(
        "mma.sync.aligned.m16n8k8.row.col.f32.tf32.tf32.f32 "
        "{%0,%1,%2,%3}, {%4,%5,%6,%7}, {%8,%9}, {%0,%1,%2,%3};"
        : "+f"(c[0]), "+f"(c[1]), "+f"(c[2]), "+f"(c[3])
        : "r"(a[0]), "r"(a[1]), "r"(a[2]), "r"(a[3]),
          "r"(b[0]), "r"(b[1]));
}

__device__ __forceinline__ void ldsm4(
    unsigned& r0, unsigned& r1, unsigned& r2, unsigned& r3, unsigned addr)
{
    asm volatile(
        "ldmatrix.sync.aligned.m8n8.x4.shared.b16 {%0,%1,%2,%3}, [%4];"
        : "=r"(r0), "=r"(r1), "=r"(r2), "=r"(r3) : "r"(addr));
}

__device__ __forceinline__ void cp16(unsigned smem_dst, const void* gsrc) {
    asm volatile("cp.async.cg.shared.global [%0], [%1], 16;\n"
                 :: "r"(smem_dst), "l"(gsrc));
}
#define CP_COMMIT() asm volatile("cp.async.commit_group;\n" ::: "memory")
#define CP_WAIT(n)  asm volatile("cp.async.wait_group %0;\n" :: "n"(n) : "memory")

// ---------------------------------------------------------------------------
// Elementwise tf32 rounding pass (float4-vectorized).
// ---------------------------------------------------------------------------
__global__ __launch_bounds__(256) void cvt_tf32(
    const float4* __restrict__ s, float4* __restrict__ d, int n4)
{
    int i = blockIdx.x * 256 + threadIdx.x;
    if (i < n4) {
        float4 v = s[i];
        d[i] = make_float4(f2tf32(v.x), f2tf32(v.y), f2tf32(v.z), f2tf32(v.w));
    }
}

// ---------------------------------------------------------------------------
// tf32 GEMM v3: 128x128 tile, 512 threads / 16 warps (32x32 warp-tile),
// 3-stage cp.async pipeline, ldmatrix A-fragments.  Inputs A, Bm must be
// pre-rounded to tf32.  C = A[M,K] @ B[K,N]; split output via C1/halfN;
// do_cvt rounds outputs to tf32.
// Smem/stage: sA 128x20 (80B rows, LDSM conflict-free), sB 16x136.
// ---------------------------------------------------------------------------
#define GEMM_SMEM (3 * (128 * 20 + 16 * 136) * 4)   // 56832 B

__global__ __launch_bounds__(512) void gemm_tc(
    const float* __restrict__ A, const float* __restrict__ Bm,
    float* __restrict__ C0, float* __restrict__ C1,
    int M, int N, int K, int halfN, int do_cvt)
{
    extern __shared__ float gsm[];
    float* sB_base = gsm + 3 * 128 * 20;

    const int t = threadIdx.x, lane = t & 31, warp = t >> 5;
    const int wm = warp >> 2, wn = warp & 3;
    const int brow = blockIdx.y * 128, bcol = blockIdx.x * 128;

    float acc[2][4][4];
    #pragma unroll
    for (int mi = 0; mi < 2; mi++)
        #pragma unroll
        for (int ni = 0; ni < 4; ni++)
            #pragma unroll
            for (int r = 0; r < 4; r++) acc[mi][ni][r] = 0.0f;

    // staging addressing: 1 cp16 for A + 1 for B per thread per stage
    const int ar = t >> 2, asub = t & 3;          // A: row 0..127, 16B chunk
    const int bk = t >> 5, bsub = t & 31;         // B: k-row 0..15, 16B chunk
    const char* Ag = (const char*)(A + (size_t)(brow + ar) * K) + asub * 16;
    const char* Bg = (const char*)(Bm + (size_t)bk * N + bcol) + bsub * 16;

    unsigned sAa = (unsigned)__cvta_generic_to_shared(gsm);
    unsigned sBa = (unsigned)__cvta_generic_to_shared(sB_base);
    const unsigned Asm = sAa + (unsigned)(ar * 80 + asub * 16);
    const unsigned Bsm = sBa + (unsigned)(bk * 544 + bsub * 16);

    const int NIT = K / 16;

    // prologue: stages 0,1
    #pragma unroll
    for (int s = 0; s < 2; s++) {
        cp16(Asm + s * 10240, Ag + s * 64);
        cp16(Bsm + s * 8704, Bg + (size_t)s * 16 * N * 4);
        CP_COMMIT();
    }

    // ldmatrix A-frag per-thread offsets (x4 = m16 x k8, verified mapping)
    const unsigned arow = (((lane >> 3) & 1) << 3) + (lane & 7);
    const unsigned akb  = (lane >> 4) << 2;

    for (int i = 0; i < NIT; i++) {
        if (i + 1 < NIT) { CP_WAIT(1); } else { CP_WAIT(0); }
        __syncthreads();
        if (i + 2 < NIT) {
            int s = (i + 2) % 3;
            cp16(Asm + s * 10240, Ag + (size_t)(i + 2) * 64);
            cp16(Bsm + s * 8704, Bg + (size_t)(i + 2) * 16 * N * 4);
            CP_COMMIT();
        }
        const int st = i % 3;
        const unsigned abase = sAa + st * 10240;
        const float* bbuf = sB_base + st * (16 * 136);

        #pragma unroll
        for (int ks = 0; ks < 16; ks += 8) {
            unsigned af[2][4];
            #pragma unroll
            for (int mi = 0; mi < 2; mi++)
                ldsm4(af[mi][0], af[mi][1], af[mi][2], af[mi][3],
                      abase + ((wm * 32 + mi * 16 + arow) * 20 + ks + akb) * 4);
            unsigned bf[4][2];
            #pragma unroll
            for (int ni = 0; ni < 4; ni++) {
                int cb = wn * 32 + ni * 8 + (lane >> 2);
                int kr = ks + (lane & 3);
                bf[ni][0] = __float_as_uint(bbuf[kr * 136 + cb]);
                bf[ni][1] = __float_as_uint(bbuf[(kr + 4) * 136 + cb]);
            }
            #pragma unroll
            for (int mi = 0; mi < 2; mi++)
                #pragma unroll
                for (int ni = 0; ni < 4; ni++)
                    mma_tf32(acc[mi][ni], af[mi], bf[ni]);
        }
    }

    #pragma unroll
    for (int mi = 0; mi < 2; mi++) {
        #pragma unroll
        for (int ni = 0; ni < 4; ni++) {
            int row = brow + wm * 32 + mi * 16 + (lane >> 2);
            int col = bcol + wn * 32 + ni * 8 + 2 * (lane & 3);
            float* dst;
            int ccol = col;
            if (C1 && col >= halfN) { dst = C1; ccol = col - halfN; }
            else                    { dst = C0; }
            float v0 = acc[mi][ni][0], v1 = acc[mi][ni][1];
            float v2 = acc[mi][ni][2], v3 = acc[mi][ni][3];
            if (do_cvt) { v0 = f2tf32(v0); v1 = f2tf32(v1);
                          v2 = f2tf32(v2); v3 = f2tf32(v3); }
            *(float2*)(dst + (size_t)row * halfN + ccol) = make_float2(v0, v1);
            *(float2*)(dst + (size_t)(row + 8) * halfN + ccol) = make_float2(v2, v3);
        }
    }
}

// ---------------------------------------------------------------------------
// LayerNorm (per-head, dim 64) + transpose to [b][h][d][skv]; tf32 output.
// ---------------------------------------------------------------------------
__global__ __launch_bounds__(256) void ln64t(
    const float* __restrict__ v, const float* __restrict__ gamma,
    const float* __restrict__ beta, float* __restrict__ vt)
{
    __shared__ float sT[64 * 68];

    int t = threadIdx.x, lane = t & 31, warp = t >> 5;
    int s0 = blockIdx.x * 64, h = blockIdx.y, b = blockIdx.z;

    float g0 = gamma[lane], g1 = gamma[lane + 32];
    float be0 = beta[lane], be1 = beta[lane + 32];

    #pragma unroll
    for (int i = 0; i < 8; i++) {
        int sl = warp * 8 + i;
        const float* p = v + ((size_t)(b * SQL + s0 + sl)) * DMODEL + h * HDIM;
        float x0 = p[lane], x1 = p[lane + 32];
        float s  = x0 + x1;
        float ss = x0 * x0 + x1 * x1;
        #pragma unroll
        for (int o = 16; o > 0; o >>= 1) {
            s  += __shfl_xor_sync(0xffffffffu, s,  o);
            ss += __shfl_xor_sync(0xffffffffu, ss, o);
        }
        float mu  = s * (1.0f / HDIM);
        float var = ss * (1.0f / HDIM) - mu * mu;
        float r   = rsqrtf(var + 1e-5f);
        sT[lane * 68 + sl]        = f2tf32((x0 - mu) * r * g0 + be0);
        sT[(lane + 32) * 68 + sl] = f2tf32((x1 - mu) * r * g1 + be1);
    }
    __syncthreads();

    int d = t >> 2, cg = (t & 3) * 16;
    float* ob = vt + ((size_t)(b * NH + h) * HDIM + d) * SQL + s0 + cg;
    #pragma unroll
    for (int i = 0; i < 4; i++)
        *(float4*)(ob + i * 4) = *(const float4*)&sT[d * 68 + cg + i * 4];
}

// ---------------------------------------------------------------------------
// Tensor-core flash sigmoid attention v5 (tf32 mma + ldmatrix), plus a
// tf32-rounded twin of the output written to qc (GEMM3's A operand).
// ---------------------------------------------------------------------------
__global__ __launch_bounds__(256, 2) void attn_tc(
    const float* __restrict__ qh, const float* __restrict__ kb,
    const float* __restrict__ vt, float* __restrict__ out,
    float* __restrict__ qc)
{
    extern __shared__ float sm[];
    float* sP = sm;                          // 128*68
    float* sK = sP + 128 * 68;               // 2*64*68
    float* sV = sK + 2 * 64 * 68;            // 2*64*68

    const int t = threadIdx.x, lane = t & 31, warp = t >> 5;
    const int qb = blockIdx.x, hd = blockIdx.y, b = blockIdx.z;
    const int q0 = qb * 128;

    const float* Qb  = qh + ((size_t)(b * SQL + q0)) * DMODEL + hd * HDIM;
    const float* Kb  = kb + ((size_t)b * SQL) * DMODEL + hd * HDIM;
    const float* Vtb = vt + ((size_t)(b * NH + hd) * HDIM) * SQL;

    unsigned sPa = (unsigned)__cvta_generic_to_shared(sP);
    unsigned sKa = (unsigned)__cvta_generic_to_shared(sK);
    unsigned sVa = (unsigned)__cvta_generic_to_shared(sV);

    // ---- stage Q ----
    {
        int r = t >> 1;
        int cgB = (t & 1) * 128;
        const char* src = (const char*)(Qb + (size_t)r * DMODEL) + cgB;
        unsigned dst = sPa + r * 272 + cgB;
        #pragma unroll
        for (int i = 0; i < 8; i++) cp16(dst + i * 16, src + i * 16);
    }
    CP_COMMIT();

    // ---- stage K / V^T tile 0 ----
    const int kr_ = t >> 2;
    const int kcB = (t & 3) * 64;
    {
        const char* ks = (const char*)(Kb + (size_t)kr_ * DMODEL) + kcB;
        const char* vs = (const char*)(Vtb + (size_t)kr_ * SQL) + kcB;
        unsigned kd = sKa + kr_ * 272 + kcB;
        unsigned vd = sVa + kr_ * 272 + kcB;
        #pragma unroll
        for (int i = 0; i < 4; i++) { cp16(kd + i * 16, ks + i * 16);
                                      cp16(vd + i * 16, vs + i * 16); }
    }
    CP_COMMIT();

    CP_WAIT(1);
    __syncwarp();

    const unsigned nb8   = (lane & 7) + ((lane >> 4) << 3);
    const unsigned kb4   = ((lane >> 3) & 1) << 2;
    const unsigned boffB = (nb8 * 68 + kb4) * 4;
    const unsigned arow  = (((lane >> 3) & 1) << 3) + (lane & 7);
    const unsigned akb   = (lane >> 4) << 2;
    const unsigned boffA = ((warp * 16 + arow) * 68 + akb) * 4;

    unsigned qf[8][4];
    #pragma unroll
    for (int kk = 0; kk < 8; kk++)
        ldsm4(qf[kk][0], qf[kk][1], qf[kk][2], qf[kk][3], sPa + boffA + kk * 32);
    __syncwarp();

    float oacc[8][4];
    #pragma unroll
    for (int ni = 0; ni < 8; ni++)
        #pragma unroll
        for (int r = 0; r < 4; r++) oacc[ni][r] = 0.0f;

    const int jmax = 2 * qb + 1;
    const int pr   = warp * 16 + (lane >> 2);
    const int qlim = q0 + warp * 16 + 15;

    for (int j = 0; j <= jmax; j++) {
        CP_WAIT(0);
        __syncthreads();
        if (j < jmax) {
            int k0n = (j + 1) * 64;
            const char* ks = (const char*)(Kb + (size_t)(k0n + kr_) * DMODEL) + kcB;
            const char* vs = (const char*)(Vtb + (size_t)kr_ * SQL + k0n) + kcB;
            unsigned kd = sKa + ((j + 1) & 1) * 17408 + kr_ * 272 + kcB;
            unsigned vd = sVa + ((j + 1) & 1) * 17408 + kr_ * 272 + kcB;
            #pragma unroll
            for (int i = 0; i < 4; i++) { cp16(kd + i * 16, ks + i * 16);
                                          cp16(vd + i * 16, vs + i * 16); }
            CP_COMMIT();
        }

        if (64 * j <= qlim) {
            unsigned kbase = sKa + (j & 1) * 17408;
            unsigned vbase = sVa + (j & 1) * 17408;

            #pragma unroll
            for (int half = 0; half < 2; half++) {
                float sfr[4][4];
                #pragma unroll
                for (int ni = 0; ni < 4; ni++)
                    #pragma unroll
                    for (int r = 0; r < 4; r++) sfr[ni][r] = 0.0f;
                #pragma unroll
                for (int kk = 0; kk < 8; kk++) {
                    #pragma unroll
                    for (int nip = 0; nip < 2; nip++) {
                        int np = half * 2 + nip;
                        unsigned b0, b1, b2, b3;
                        ldsm4(b0, b1, b2, b3,
                              kbase + np * 4352 + kk * 32 + boffB);
                        unsigned bl[2] = { b0, b1 }, bh[2] = { b2, b3 };
                        mma_tf32(sfr[nip * 2 + 0], qf[kk], bl);
                        mma_tf32(sfr[nip * 2 + 1], qf[kk], bh);
                    }
                }
                int g0 = q0 + pr, g1 = g0 + 8;
                #pragma unroll
                for (int n4 = 0; n4 < 4; n4++) {
                    int ni = half * 4 + n4;
                    int c  = ni * 8 + 2 * (lane & 3);
                    int gc = j * 64 + c;
                    float e0 = exp2f(fmaf(sfr[n4][0], -0.18033688f, 11.5415603f));
                    float e1 = exp2f(fmaf(sfr[n4][1], -0.18033688f, 11.5415603f));
                    float e2 = exp2f(fmaf(sfr[n4][2], -0.18033688f, 11.5415603f));
                    float e3 = exp2f(fmaf(sfr[n4][3], -0.18033688f, 11.5415603f));
                    float p00 = __fdividef(1.f, 1.f + e0);
                    float p01 = __fdividef(1.f, 1.f + e1);
                    float p10 = __fdividef(1.f, 1.f + e2);
                    float p11 = __fdividef(1.f, 1.f + e3);
                    p00 = (gc     <= g0) ? p00 : 0.f;
                    p01 = (gc + 1 <= g0) ? p01 : 0.f;
                    p10 = (gc     <= g1) ? p10 : 0.f;
                    p11 = (gc + 1 <= g1) ? p11 : 0.f;
                    *(float2*)&sP[pr * 68 + c] =
                        make_float2(f2tf32(p00), f2tf32(p01));
                    *(float2*)&sP[(pr + 8) * 68 + c] =
                        make_float2(f2tf32(p10), f2tf32(p11));
                }
            }
            __syncwarp();

            #pragma unroll
            for (int kk = 0; kk < 8; kk++) {
                unsigned pf[4];
                ldsm4(pf[0], pf[1], pf[2], pf[3], sPa + boffA + kk * 32);
                #pragma unroll
                for (int np = 0; np < 4; np++) {
                    unsigned b0, b1, b2, b3;
                    ldsm4(b0, b1, b2, b3,
                          vbase + np * 4352 + kk * 32 + boffB);
                    unsigned bl[2] = { b0, b1 }, bh[2] = { b2, b3 };
                    mma_tf32(oacc[np * 2 + 0], pf, bl);
                    mma_tf32(oacc[np * 2 + 1], pf, bh);
                }
            }
        }
    }

    // ---- epilogue: fp32 to out, tf32 twin to qc (feeds GEMM3) ----
    {
        size_t rowoff = ((size_t)(b * SQL + q0 + pr)) * DMODEL + hd * HDIM;
        float* ob = out + rowoff;
        float* pc = qc + rowoff;
        #pragma unroll
        for (int ni = 0; ni < 8; ni++) {
            int c = ni * 8 + 2 * (lane & 3);
            *(float2*)(ob + c) = make_float2(oacc[ni][0], oacc[ni][1]);
            *(float2*)(ob + (size_t)8 * DMODEL + c) =
                make_float2(oacc[ni][2], oacc[ni][3]);
            *(float2*)(pc + c) =
                make_float2(f2tf32(oacc[ni][0]), f2tf32(oacc[ni][1]));
            *(float2*)(pc + (size_t)8 * DMODEL + c) =
                make_float2(f2tf32(oacc[ni][2]), f2tf32(oacc[ni][3]));
        }
    }
}

#define ATTN_SMEM ((128 * 68 + 2 * 64 * 68 + 2 * 64 * 68) * 4)   // 104448 B

// ---------------------------------------------------------------------------
extern "C" void kernel_launch(void* const* d_in, const int* in_sizes, int n_in,
                              void* d_out, int out_size)
{
    const float* q     = (const float*)d_in[0];
    const float* kv    = (const float*)d_in[1];
    const float* Wq    = (const float*)d_in[2];
    const float* Wkv   = (const float*)d_in[3];
    const float* gamma = (const float*)d_in[4];
    const float* beta  = (const float*)d_in[5];
    const float* Wproj = (const float*)d_in[6];
    float* out = (float*)d_out;

    float *qh, *kbuf, *vbuf, *vtbuf, *qc, *kvc, *wbuf;
    cudaGetSymbolAddress((void**)&qh,    g_qh);
    cudaGetSymbolAddress((void**)&kbuf,  g_k);
    cudaGetSymbolAddress((void**)&vbuf,  g_v);
    cudaGetSymbolAddress((void**)&vtbuf, g_vt);
    cudaGetSymbolAddress((void**)&qc,    g_qc);
    cudaGetSymbolAddress((void**)&kvc,   g_kvc);
    cudaGetSymbolAddress((void**)&wbuf,  g_w);

    cudaFuncSetAttribute(attn_tc,
        cudaFuncAttributeMaxDynamicSharedMemorySize, ATTN_SMEM);
    cudaFuncSetAttribute(gemm_tc,
        cudaFuncAttributeMaxDynamicSharedMemorySize, GEMM_SMEM);

    const int M  = NB * SQL;                 // 4096
    const int D2 = DMODEL * DMODEL;          // 1,048,576

    // 0) tf32 pre-rounding of GEMM inputs (rna, same as old staging cvt)
    cvt_tf32<<<(M * DMODEL / 4 + 255) / 256, 256>>>(
        (const float4*)q, (float4*)qc, M * DMODEL / 4);
    cvt_tf32<<<(M * DMODEL / 4 + 255) / 256, 256>>>(
        (const float4*)kv, (float4*)kvc, M * DMODEL / 4);
    cvt_tf32<<<(D2 / 4 + 255) / 256, 256>>>(
        (const float4*)Wq, (float4*)wbuf, D2 / 4);
    cvt_tf32<<<(2 * D2 / 4 + 255) / 256, 256>>>(
        (const float4*)Wkv, (float4*)(wbuf + (size_t)D2), 2 * D2 / 4);
    cvt_tf32<<<(D2 / 4 + 255) / 256, 256>>>(
        (const float4*)Wproj, (float4*)(wbuf + (size_t)3 * D2), D2 / 4);

    // 1) qh = q @ Wq  (tf32-rounded output)
    gemm_tc<<<dim3(DMODEL / 128, M / 128), 512, GEMM_SMEM>>>(
        qc, wbuf, qh, nullptr, M, DMODEL, DMODEL, DMODEL, 1);

    // 2) kvh = kv @ Wkv, split K / V (tf32-rounded)
    gemm_tc<<<dim3(2 * DMODEL / 128, M / 128), 512, GEMM_SMEM>>>(
        kvc, wbuf + (size_t)D2, kbuf, vbuf, M, 2 * DMODEL, DMODEL, DMODEL, 1);

    // 3) per-head LayerNorm of V + transpose into g_vt (tf32)
    ln64t<<<dim3(SQL / 64, NH, NB), 256>>>(vbuf, gamma, beta, vtbuf);

    // 4) attention -> attn_times_v (fp32 to out) + tf32 twin into qc
    attn_tc<<<dim3(SQL / 128, NH, NB), 256, ATTN_SMEM>>>(
        qh, kbuf, vtbuf, out, qc);

    // 5) attn_proj = tf32(attn_times_v) @ Wproj (fp32 out)
    gemm_tc<<<dim3(DMODEL / 128, M / 128), 512, GEMM_SMEM>>>(
        qc, wbuf + (size_t)3 * D2, out + (size_t)M * DMODEL, nullptr,
        M, DMODEL, DMODEL, DMODEL, 0);
}

// round 12
// speedup vs baseline: 1.1388x; 1.0524x over previous
#include <cuda_runtime.h>
#include <cuda_bf16.h>

#define SQL 2048
#define DMODEL 1024
#define NB 2
#define NH 16
#define HDIM 64

// Scratch (allocation-free rule: __device__ globals)
__device__ float g_qh [(size_t)NB * SQL * DMODEL];
__device__ float g_k  [(size_t)NB * SQL * DMODEL];
__device__ float g_v  [(size_t)NB * SQL * DMODEL];
__device__ float g_vt [(size_t)NB * NH * HDIM * SQL];   // V^T per head
__device__ float g_qc [(size_t)NB * SQL * DMODEL];      // tf32(q); later tf32(attn_out)
__device__ float g_kvc[(size_t)NB * SQL * DMODEL];      // tf32(kv)
__device__ float g_w  [(size_t)4 * DMODEL * DMODEL];    // tf32 W: [Wq | Wkv(2) | Wproj]

// ---------------------------------------------------------------------------
// tf32 / cp.async / ldmatrix helpers
// ---------------------------------------------------------------------------
__device__ __forceinline__ float f2tf32(float x) {
    unsigned u;
    asm("cvt.rna.tf32.f32 %0, %1;" : "=r"(u) : "f"(x));
    return __uint_as_float(u);
}

__device__ __forceinline__ void mma_tf32(
    float* c, const unsigned* a, const unsigned* b)
{
    asm volatile(
        "mma.sync.aligned.m16n8k8.row.col.f32.tf32.tf32.f32 "
        "{%0,%1,%2,%3}, {%4,%5,%6,%7}, {%8,%9}, {%0,%1,%2,%3};"
        : "+f"(c[0]), "+f"(c[1]), "+f"(c[2]), "+f"(c[3])
        : "r"(a[0]), "r"(a[1]), "r"(a[2]), "r"(a[3]),
          "r"(b[0]), "r"(b[1]));
}

__device__ __forceinline__ void ldsm4(
    unsigned& r0, unsigned& r1, unsigned& r2, unsigned& r3, unsigned addr)
{
    asm volatile(
        "ldmatrix.sync.aligned.m8n8.x4.shared.b16 {%0,%1,%2,%3}, [%4];"
        : "=r"(r0), "=r"(r1), "=r"(r2), "=r"(r3) : "r"(addr));
}

__device__ __forceinline__ void cp16(unsigned smem_dst, const void* gsrc) {
    asm volatile("cp.async.cg.shared.global [%0], [%1], 16;\n"
                 :: "r"(smem_dst), "l"(gsrc));
}
#define CP_COMMIT() asm volatile("cp.async.commit_group;\n" ::: "memory")
#define CP_WAIT(n)  asm volatile("cp.async.wait_group %0;\n" :: "n"(n) : "memory")

// ---------------------------------------------------------------------------
// Fused tf32 rounding pass over all 5 GEMM inputs (one launch).
// Segments (in float4 units):
//   [0, NQ4)        q     -> qc
//   [NQ4, 2*NQ4)    kv    -> kvc
//   [.., +NW4)      Wq    -> w[0]
//   [.., +2*NW4)    Wkv   -> w[NW4]
//   [.., +NW4)      Wproj -> w[3*NW4]
// ---------------------------------------------------------------------------
#define NQ4  ((size_t)NB * SQL * DMODEL / 4)
#define NW4  ((size_t)DMODEL * DMODEL / 4)

__global__ __launch_bounds__(256) void cvt_all(
    const float4* __restrict__ q,  const float4* __restrict__ kv,
    const float4* __restrict__ wq, const float4* __restrict__ wkv,
    const float4* __restrict__ wp,
    float4* __restrict__ qc, float4* __restrict__ kvc,
    float4* __restrict__ w)
{
    size_t i = (size_t)blockIdx.x * 256 + threadIdx.x;
    const size_t A1 = NQ4, A2 = A1 + NQ4, A3 = A2 + NW4,
                 A4 = A3 + 2 * NW4, A5 = A4 + NW4;
    const float4* s;  float4* d;  size_t off;
    if      (i < A1) { s = q;   d = qc;            off = i; }
    else if (i < A2) { s = kv;  d = kvc;           off = i - A1; }
    else if (i < A3) { s = wq;  d = w;             off = i - A2; }
    else if (i < A4) { s = wkv; d = w + NW4;       off = i - A3; }
    else if (i < A5) { s = wp;  d = w + 3 * NW4;   off = i - A4; }
    else return;
    float4 v = s[off];
    d[off] = make_float4(f2tf32(v.x), f2tf32(v.y), f2tf32(v.z), f2tf32(v.w));
}

// ---------------------------------------------------------------------------
// tf32 GEMM v4: 128x128 tile, 256 threads / 8 warps (64x32 warp-tile),
// 3-stage cp.async pipeline, ldmatrix A-fragments, 2 CTAs/SM
// (independent barrier domains hide each other's sync/wait stalls).
// Inputs A, Bm pre-rounded to tf32.  C = A[M,K] @ B[K,N]; split via
// C1/halfN; do_cvt rounds outputs to tf32.
// ---------------------------------------------------------------------------
#define GEMM_SMEM (3 * (128 * 20 + 16 * 136) * 4)   // 56832 B

__global__ __launch_bounds__(256, 2) void gemm_tc(
    const float* __restrict__ A, const float* __restrict__ Bm,
    float* __restrict__ C0, float* __restrict__ C1,
    int M, int N, int K, int halfN, int do_cvt)
{
    extern __shared__ float gsm[];
    float* sB_base = gsm + 3 * 128 * 20;

    const int t = threadIdx.x, lane = t & 31, warp = t >> 5;
    const int wm = warp >> 2, wn = warp & 3;
    const int brow = blockIdx.y * 128, bcol = blockIdx.x * 128;

    float acc[4][4][4];
    #pragma unroll
    for (int mi = 0; mi < 4; mi++)
        #pragma unroll
        for (int ni = 0; ni < 4; ni++)
            #pragma unroll
            for (int r = 0; r < 4; r++) acc[mi][ni][r] = 0.0f;

    // staging: A tile 128x16 f = 512 cp16 -> 2/thread (rows r, r+64)
    //          B tile 16x128 f = 512 cp16 -> 2/thread (k-rows k, k+8)
    const int ar = t >> 2, asub = t & 3;
    const int bk = t >> 5, bsub = t & 31;
    const char* Ag0 = (const char*)(A + (size_t)(brow + ar) * K) + asub * 16;
    const char* Ag1 = Ag0 + (size_t)64 * K * 4;
    const char* Bg0 = (const char*)(Bm + (size_t)bk * N + bcol) + bsub * 16;
    const char* Bg1 = Bg0 + (size_t)8 * N * 4;

    unsigned sAa = (unsigned)__cvta_generic_to_shared(gsm);
    unsigned sBa = (unsigned)__cvta_generic_to_shared(sB_base);
    const unsigned Asm0 = sAa + (unsigned)(ar * 80 + asub * 16);
    const unsigned Asm1 = Asm0 + 64 * 80;
    const unsigned Bsm0 = sBa + (unsigned)(bk * 544 + bsub * 16);
    const unsigned Bsm1 = Bsm0 + 8 * 544;

    const int NIT = K / 16;

    #pragma unroll
    for (int s = 0; s < 2; s++) {
        cp16(Asm0 + s * 10240, Ag0 + s * 64);
        cp16(Asm1 + s * 10240, Ag1 + s * 64);
        cp16(Bsm0 + s * 8704, Bg0 + (size_t)s * 16 * N * 4);
        cp16(Bsm1 + s * 8704, Bg1 + (size_t)s * 16 * N * 4);
        CP_COMMIT();
    }

    // ldmatrix A-frag per-thread offsets (x4 = m16 x k8)
    const unsigned arow = (((lane >> 3) & 1) << 3) + (lane & 7);
    const unsigned akb  = (lane >> 4) << 2;

    for (int i = 0; i < NIT; i++) {
        if (i + 1 < NIT) { CP_WAIT(1); } else { CP_WAIT(0); }
        __syncthreads();
        if (i + 2 < NIT) {
            int s = (i + 2) % 3;
            cp16(Asm0 + s * 10240, Ag0 + (size_t)(i + 2) * 64);
            cp16(Asm1 + s * 10240, Ag1 + (size_t)(i + 2) * 64);
            cp16(Bsm0 + s * 8704, Bg0 + (size_t)(i + 2) * 16 * N * 4);
            cp16(Bsm1 + s * 8704, Bg1 + (size_t)(i + 2) * 16 * N * 4);
            CP_COMMIT();
        }
        const int st = i % 3;
        const unsigned abase = sAa + st * 10240;
        const float* bbuf = sB_base + st * (16 * 136);

        #pragma unroll
        for (int ks = 0; ks < 16; ks += 8) {
            unsigned af[4][4];
            #pragma unroll
            for (int mi = 0; mi < 4; mi++)
                ldsm4(af[mi][0], af[mi][1], af[mi][2], af[mi][3],
                      abase + ((wm * 64 + mi * 16 + arow) * 20 + ks + akb) * 4);
            unsigned bf[4][2];
            #pragma unroll
            for (int ni = 0; ni < 4; ni++) {
                int cb = wn * 32 + ni * 8 + (lane >> 2);
                int kr = ks + (lane & 3);
                bf[ni][0] = __float_as_uint(bbuf[kr * 136 + cb]);
                bf[ni][1] = __float_as_uint(bbuf[(kr + 4) * 136 + cb]);
            }
            #pragma unroll
            for (int mi = 0; mi < 4; mi++)
                #pragma unroll
                for (int ni = 0; ni < 4; ni++)
                    mma_tf32(acc[mi][ni], af[mi], bf[ni]);
        }
    }

    #pragma unroll
    for (int mi = 0; mi < 4; mi++) {
        #pragma unroll
        for (int ni = 0; ni < 4; ni++) {
            int row = brow + wm * 64 + mi * 16 + (lane >> 2);
            int col = bcol + wn * 32 + ni * 8 + 2 * (lane & 3);
            float* dst;
            int ccol = col;
            if (C1 && col >= halfN) { dst = C1; ccol = col - halfN; }
            else                    { dst = C0; }
            float v0 = acc[mi][ni][0], v1 = acc[mi][ni][1];
            float v2 = acc[mi][ni][2], v3 = acc[mi][ni][3];
            if (do_cvt) { v0 = f2tf32(v0); v1 = f2tf32(v1);
                          v2 = f2tf32(v2); v3 = f2tf32(v3); }
            *(float2*)(dst + (size_t)row * halfN + ccol) = make_float2(v0, v1);
            *(float2*)(dst + (size_t)(row + 8) * halfN + ccol) = make_float2(v2, v3);
        }
    }
}

// ---------------------------------------------------------------------------
// LayerNorm (per-head, dim 64) + transpose to [b][h][d][skv]; tf32 output.
// ---------------------------------------------------------------------------
__global__ __launch_bounds__(256) void ln64t(
    const float* __restrict__ v, const float* __restrict__ gamma,
    const float* __restrict__ beta, float* __restrict__ vt)
{
    __shared__ float sT[64 * 68];

    int t = threadIdx.x, lane = t & 31, warp = t >> 5;
    int s0 = blockIdx.x * 64, h = blockIdx.y, b = blockIdx.z;

    float g0 = gamma[lane], g1 = gamma[lane + 32];
    float be0 = beta[lane], be1 = beta[lane + 32];

    #pragma unroll
    for (int i = 0; i < 8; i++) {
        int sl = warp * 8 + i;
        const float* p = v + ((size_t)(b * SQL + s0 + sl)) * DMODEL + h * HDIM;
        float x0 = p[lane], x1 = p[lane + 32];
        float s  = x0 + x1;
        float ss = x0 * x0 + x1 * x1;
        #pragma unroll
        for (int o = 16; o > 0; o >>= 1) {
            s  += __shfl_xor_sync(0xffffffffu, s,  o);
            ss += __shfl_xor_sync(0xffffffffu, ss, o);
        }
        float mu  = s * (1.0f / HDIM);
        float var = ss * (1.0f / HDIM) - mu * mu;
        float r   = rsqrtf(var + 1e-5f);
        sT[lane * 68 + sl]        = f2tf32((x0 - mu) * r * g0 + be0);
        sT[(lane + 32) * 68 + sl] = f2tf32((x1 - mu) * r * g1 + be1);
    }
    __syncthreads();

    int d = t >> 2, cg = (t & 3) * 16;
    float* ob = vt + ((size_t)(b * NH + h) * HDIM + d) * SQL + s0 + cg;
    #pragma unroll
    for (int i = 0; i < 4; i++)
        *(float4*)(ob + i * 4) = *(const float4*)&sT[d * 68 + cg + i * 4];
}

// ---------------------------------------------------------------------------
// Tensor-core flash sigmoid attention v5 (tf32 mma + ldmatrix), plus a
// tf32-rounded twin of the output written to qc (GEMM3's A operand).
// ---------------------------------------------------------------------------
__global__ __launch_bounds__(256, 2) void attn_tc(
    const float* __restrict__ qh, const float* __restrict__ kb,
    const float* __restrict__ vt, float* __restrict__ out,
    float* __restrict__ qc)
{
    extern __shared__ float sm[];
    float* sP = sm;                          // 128*68
    float* sK = sP + 128 * 68;               // 2*64*68
    float* sV = sK + 2 * 64 * 68;            // 2*64*68

    const int t = threadIdx.x, lane = t & 31, warp = t >> 5;
    const int qb = blockIdx.x, hd = blockIdx.y, b = blockIdx.z;
    const int q0 = qb * 128;

    const float* Qb  = qh + ((size_t)(b * SQL + q0)) * DMODEL + hd * HDIM;
    const float* Kb  = kb + ((size_t)b * SQL) * DMODEL + hd * HDIM;
    const float* Vtb = vt + ((size_t)(b * NH + hd) * HDIM) * SQL;

    unsigned sPa = (unsigned)__cvta_generic_to_shared(sP);
    unsigned sKa = (unsigned)__cvta_generic_to_shared(sK);
    unsigned sVa = (unsigned)__cvta_generic_to_shared(sV);

    // ---- stage Q ----
    {
        int r = t >> 1;
        int cgB = (t & 1) * 128;
        const char* src = (const char*)(Qb + (size_t)r * DMODEL) + cgB;
        unsigned dst = sPa + r * 272 + cgB;
        #pragma unroll
        for (int i = 0; i < 8; i++) cp16(dst + i * 16, src + i * 16);
    }
    CP_COMMIT();

    // ---- stage K / V^T tile 0 ----
    const int kr_ = t >> 2;
    const int kcB = (t & 3) * 64;
    {
        const char* ks = (const char*)(Kb + (size_t)kr_ * DMODEL) + kcB;
        const char* vs = (const char*)(Vtb + (size_t)kr_ * SQL) + kcB;
        unsigned kd = sKa + kr_ * 272 + kcB;
        unsigned vd = sVa + kr_ * 272 + kcB;
        #pragma unroll
        for (int i = 0; i < 4; i++) { cp16(kd + i * 16, ks + i * 16);
                                      cp16(vd + i * 16, vs + i * 16); }
    }
    CP_COMMIT();

    CP_WAIT(1);
    __syncwarp();

    const unsigned nb8   = (lane & 7) + ((lane >> 4) << 3);
    const unsigned kb4   = ((lane >> 3) & 1) << 2;
    const unsigned boffB = (nb8 * 68 + kb4) * 4;
    const unsigned arow  = (((lane >> 3) & 1) << 3) + (lane & 7);
    const unsigned akb   = (lane >> 4) << 2;
    const unsigned boffA = ((warp * 16 + arow) * 68 + akb) * 4;

    unsigned qf[8][4];
    #pragma unroll
    for (int kk = 0; kk < 8; kk++)
        ldsm4(qf[kk][0], qf[kk][1], qf[kk][2], qf[kk][3], sPa + boffA + kk * 32);
    __syncwarp();

    float oacc[8][4];
    #pragma unroll
    for (int ni = 0; ni < 8; ni++)
        #pragma unroll
        for (int r = 0; r < 4; r++) oacc[ni][r] = 0.0f;

    const int jmax = 2 * qb + 1;
    const int pr   = warp * 16 + (lane >> 2);
    const int qlim = q0 + warp * 16 + 15;

    for (int j = 0; j <= jmax; j++) {
        CP_WAIT(0);
        __syncthreads();
        if (j < jmax) {
            int k0n = (j + 1) * 64;
            const char* ks = (const char*)(Kb + (size_t)(k0n + kr_) * DMODEL) + kcB;
            const char* vs = (const char*)(Vtb + (size_t)kr_ * SQL + k0n) + kcB;
            unsigned kd = sKa + ((j + 1) & 1) * 17408 + kr_ * 272 + kcB;
            unsigned vd = sVa + ((j + 1) & 1) * 17408 + kr_ * 272 + kcB;
            #pragma unroll
            for (int i = 0; i < 4; i++) { cp16(kd + i * 16, ks + i * 16);
                                          cp16(vd + i * 16, vs + i * 16); }
            CP_COMMIT();
        }

        if (64 * j <= qlim) {
            unsigned kbase = sKa + (j & 1) * 17408;
            unsigned vbase = sVa + (j & 1) * 17408;

            #pragma unroll
            for (int half = 0; half < 2; half++) {
                float sfr[4][4];
                #pragma unroll
                for (int ni = 0; ni < 4; ni++)
                    #pragma unroll
                    for (int r = 0; r < 4; r++) sfr[ni][r] = 0.0f;
                #pragma unroll
                for (int kk = 0; kk < 8; kk++) {
                    #pragma unroll
                    for (int nip = 0; nip < 2; nip++) {
                        int np = half * 2 + nip;
                        unsigned b0, b1, b2, b3;
                        ldsm4(b0, b1, b2, b3,
                              kbase + np * 4352 + kk * 32 + boffB);
                        unsigned bl[2] = { b0, b1 }, bh[2] = { b2, b3 };
                        mma_tf32(sfr[nip * 2 + 0], qf[kk], bl);
                        mma_tf32(sfr[nip * 2 + 1], qf[kk], bh);
                    }
                }
                int g0 = q0 + pr, g1 = g0 + 8;
                #pragma unroll
                for (int n4 = 0; n4 < 4; n4++) {
                    int ni = half * 4 + n4;
                    int c  = ni * 8 + 2 * (lane & 3);
                    int gc = j * 64 + c;
                    float e0 = exp2f(fmaf(sfr[n4][0], -0.18033688f, 11.5415603f));
                    float e1 = exp2f(fmaf(sfr[n4][1], -0.18033688f, 11.5415603f));
                    float e2 = exp2f(fmaf(sfr[n4][2], -0.18033688f, 11.5415603f));
                    float e3 = exp2f(fmaf(sfr[n4][3], -0.18033688f, 11.5415603f));
                    float p00 = __fdividef(1.f, 1.f + e0);
                    float p01 = __fdividef(1.f, 1.f + e1);
                    float p10 = __fdividef(1.f, 1.f + e2);
                    float p11 = __fdividef(1.f, 1.f + e3);
                    p00 = (gc     <= g0) ? p00 : 0.f;
                    p01 = (gc + 1 <= g0) ? p01 : 0.f;
                    p10 = (gc     <= g1) ? p10 : 0.f;
                    p11 = (gc + 1 <= g1) ? p11 : 0.f;
                    *(float2*)&sP[pr * 68 + c] =
                        make_float2(f2tf32(p00), f2tf32(p01));
                    *(float2*)&sP[(pr + 8) * 68 + c] =
                        make_float2(f2tf32(p10), f2tf32(p11));
                }
            }
            __syncwarp();

            #pragma unroll
            for (int kk = 0; kk < 8; kk++) {
                unsigned pf[4];
                ldsm4(pf[0], pf[1], pf[2], pf[3], sPa + boffA + kk * 32);
                #pragma unroll
                for (int np = 0; np < 4; np++) {
                    unsigned b0, b1, b2, b3;
                    ldsm4(b0, b1, b2, b3,
                          vbase + np * 4352 + kk * 32 + boffB);
                    unsigned bl[2] = { b0, b1 }, bh[2] = { b2, b3 };
                    mma_tf32(oacc[np * 2 + 0], pf, bl);
                    mma_tf32(oacc[np * 2 + 1], pf, bh);
                }
            }
        }
    }

    // ---- epilogue: fp32 to out, tf32 twin to qc (feeds GEMM3) ----
    {
        size_t rowoff = ((size_t)(b * SQL + q0 + pr)) * DMODEL + hd * HDIM;
        float* ob = out + rowoff;
        float* pc = qc + rowoff;
        #pragma unroll
        for (int ni = 0; ni < 8; ni++) {
            int c = ni * 8 + 2 * (lane & 3);
            *(float2*)(ob + c) = make_float2(oacc[ni][0], oacc[ni][1]);
            *(float2*)(ob + (size_t)8 * DMODEL + c) =
                make_float2(oacc[ni][2], oacc[ni][3]);
            *(float2*)(pc + c) =
                make_float2(f2tf32(oacc[ni][0]), f2tf32(oacc[ni][1]));
            *(float2*)(pc + (size_t)8 * DMODEL + c) =
                make_float2(f2tf32(oacc[ni][2]), f2tf32(oacc[ni][3]));
        }
    }
}

#define ATTN_SMEM ((128 * 68 + 2 * 64 * 68 + 2 * 64 * 68) * 4)   // 104448 B

// ---------------------------------------------------------------------------
extern "C" void kernel_launch(void* const* d_in, const int* in_sizes, int n_in,
                              void* d_out, int out_size)
{
    const float* q     = (const float*)d_in[0];
    const float* kv    = (const float*)d_in[1];
    const float* Wq    = (const float*)d_in[2];
    const float* Wkv   = (const float*)d_in[3];
    const float* gamma = (const float*)d_in[4];
    const float* beta  = (const float*)d_in[5];
    const float* Wproj = (const float*)d_in[6];
    float* out = (float*)d_out;

    float *qh, *kbuf, *vbuf, *vtbuf, *qc, *kvc, *wbuf;
    cudaGetSymbolAddress((void**)&qh,    g_qh);
    cudaGetSymbolAddress((void**)&kbuf,  g_k);
    cudaGetSymbolAddress((void**)&vbuf,  g_v);
    cudaGetSymbolAddress((void**)&vtbuf, g_vt);
    cudaGetSymbolAddress((void**)&qc,    g_qc);
    cudaGetSymbolAddress((void**)&kvc,   g_kvc);
    cudaGetSymbolAddress((void**)&wbuf,  g_w);

    cudaFuncSetAttribute(attn_tc,
        cudaFuncAttributeMaxDynamicSharedMemorySize, ATTN_SMEM);
    cudaFuncSetAttribute(gemm_tc,
        cudaFuncAttributeMaxDynamicSharedMemorySize, GEMM_SMEM);

    const int M  = NB * SQL;                 // 4096
    const size_t D2 = (size_t)DMODEL * DMODEL;

    // 0) fused tf32 pre-rounding of all GEMM inputs (one launch)
    {
        size_t total4 = 2 * NQ4 + 4 * NW4;
        cvt_all<<<(unsigned)((total4 + 255) / 256), 256>>>(
            (const float4*)q, (const float4*)kv,
            (const float4*)Wq, (const float4*)Wkv, (const float4*)Wproj,
            (float4*)qc, (float4*)kvc, (float4*)wbuf);
    }

    // 1) qh = q @ Wq  (tf32-rounded output)
    gemm_tc<<<dim3(DMODEL / 128, M / 128), 256, GEMM_SMEM>>>(
        qc, wbuf, qh, nullptr, M, DMODEL, DMODEL, DMODEL, 1);

    // 2) kvh = kv @ Wkv, split K / V (tf32-rounded)
    gemm_tc<<<dim3(2 * DMODEL / 128, M / 128), 256, GEMM_SMEM>>>(
        kvc, wbuf + D2, kbuf, vbuf, M, 2 * DMODEL, DMODEL, DMODEL, 1);

    // 3) per-head LayerNorm of V + transpose into g_vt (tf32)
    ln64t<<<dim3(SQL / 64, NH, NB), 256>>>(vbuf, gamma, beta, vtbuf);

    // 4) attention -> attn_times_v (fp32 to out) + tf32 twin into qc
    attn_tc<<<dim3(SQL / 128, NH, NB), 256, ATTN_SMEM>>>(
        qh, kbuf, vtbuf, out, qc);

    // 5) attn_proj = tf32(attn_times_v) @ Wproj (fp32 out)
    gemm_tc<<<dim3(DMODEL / 128, M / 128), 256, GEMM_SMEM>>>(
        qc, wbuf + 3 * D2, out + (size_t)M * DMODEL, nullptr,
        M, DMODEL, DMODEL, DMODEL, 0);
}